// round 11
// baseline (speedup 1.0000x reference)
#include <cuda_runtime.h>
#include <cuda_bf16.h>

#define D 8192
#define BATCH 4096
#define ROWS_PER_BLOCK 16

__device__ float d_z[D];   // after FWHT bits 10..12, s1[0] folded
__device__ float d_w[D];   // final weight row

// ---------------------------------------------------------------------------
// K1 (R9's proven stageA): softplus + s1[0] + FWHT bits 10..12 (strides
// 1024/2048/4096). Thread i owns {i + j*1024 : j=0..7}; every warp access is
// a perfect contiguous segment. Barrier-free, register-only. 16 x 64.
// ---------------------------------------------------------------------------
__global__ __launch_bounds__(64, 1)
void stage1_kernel(const float* __restrict__ s1,
                   const float* __restrict__ g_mu,
                   const float* __restrict__ g_rho,
                   const float* __restrict__ eps) {
    const int i = blockIdx.x * 64 + threadIdx.x;     // 0..1023
    const float s10 = __ldg(s1);

    float rh[8], mu[8], ep[8];
    #pragma unroll
    for (int j = 0; j < 8; j++) {                    // issue all loads first
        rh[j] = __ldg(g_rho + i + j * 1024);
        mu[j] = __ldg(g_mu  + i + j * 1024);
        ep[j] = __ldg(eps   + i + j * 1024);
    }
    float r[8];
    #pragma unroll
    for (int j = 0; j < 8; j++) {
        float sp = fmaxf(rh[j], 0.0f) + __logf(1.0f + __expf(-fabsf(rh[j])));
        r[j] = s10 * fmaf(sp, ep[j], mu[j]);
    }
    #pragma unroll
    for (int s = 1; s < 8; s <<= 1) {                // bits 10..12
        #pragma unroll
        for (int j = 0; j < 8; j++) {
            if (!(j & s)) {
                float a = r[j], b = r[j | s];
                r[j]     = a + b;
                r[j | s] = a - b;
            }
        }
    }
    #pragma unroll
    for (int j = 0; j < 8; j++)
        d_z[i + j * 1024] = r[j];                    // coalesced
}

// ---------------------------------------------------------------------------
// K2: FWHT bits 0..9 + s2 scale, barrier-free. Element i = s*1024 + c*128 +
// k*32 + lane (s = blockIdx, c: regs bits 7..9, k: regs bits 5..6, lane:
// bits 0..4 -> coalesced loads AND shfl butterflies). 8 blocks x 32 threads,
// 32 data regs/thread. s2 preloaded before the PDL dependency sync.
// ---------------------------------------------------------------------------
__global__ __launch_bounds__(32, 1)
void stage2_kernel(const float* __restrict__ s2) {
    const int lane = threadIdx.x;
    const int sb   = blockIdx.x * 1024;

    // prologue independent of K1
    float s2v[8][4];
    #pragma unroll
    for (int c = 0; c < 8; c++)
        #pragma unroll
        for (int k = 0; k < 4; k++)
            s2v[c][k] = __ldg(s2 + sb + c * 128 + k * 32 + lane);

#if __CUDA_ARCH__ >= 900
    cudaGridDependencySynchronize();                 // wait for d_z
#endif

    float v[8][4];
    #pragma unroll
    for (int c = 0; c < 8; c++)
        #pragma unroll
        for (int k = 0; k < 4; k++)
            v[c][k] = d_z[sb + c * 128 + k * 32 + lane];

    // bits 0..4 via shfl.xor on lane
    #pragma unroll
    for (int m = 1; m <= 16; m <<= 1) {
        const float sgn = (lane & m) ? -1.0f : 1.0f;
        #pragma unroll
        for (int c = 0; c < 8; c++)
            #pragma unroll
            for (int k = 0; k < 4; k++) {
                float o = __shfl_xor_sync(0xffffffffu, v[c][k], m);
                v[c][k] = fmaf(sgn, v[c][k], o);
            }
    }
    // bits 5..6 over k
    #pragma unroll
    for (int c = 0; c < 8; c++) {
        { float a0 = v[c][0], b0 = v[c][1], a1 = v[c][2], b1 = v[c][3];
          v[c][0] = a0 + b0; v[c][1] = a0 - b0;
          v[c][2] = a1 + b1; v[c][3] = a1 - b1; }
        { float a0 = v[c][0], b0 = v[c][2], a1 = v[c][1], b1 = v[c][3];
          v[c][0] = a0 + b0; v[c][2] = a0 - b0;
          v[c][1] = a1 + b1; v[c][3] = a1 - b1; }
    }
    // bits 7..9 over c
    #pragma unroll
    for (int s = 1; s < 8; s <<= 1) {
        #pragma unroll
        for (int c = 0; c < 8; c++) {
            if (!(c & s)) {
                #pragma unroll
                for (int k = 0; k < 4; k++) {
                    float a = v[c][k], b = v[c | s][k];
                    v[c][k]     = a + b;
                    v[c | s][k] = a - b;
                }
            }
        }
    }

    #pragma unroll
    for (int c = 0; c < 8; c++)
        #pragma unroll
        for (int k = 0; k < 4; k++)
            d_w[sb + c * 128 + k * 32 + lane] = s2v[c][k] * v[c][k];
}

// ---------------------------------------------------------------------------
// K3: pure outer product (R1's body, measured 20.8us — at the store roofline).
// out[b][j] = x[b] * w[j].  grid (8,256) x 256, 16 rows/block, __stcs.
// ---------------------------------------------------------------------------
__global__ __launch_bounds__(256)
void outer_kernel(const float* __restrict__ x, float* __restrict__ out) {
    const int jbase = blockIdx.x * 1024 + threadIdx.x * 4;
    const int b0    = blockIdx.y * ROWS_PER_BLOCK;

    float xs[ROWS_PER_BLOCK];
    #pragma unroll
    for (int q = 0; q < ROWS_PER_BLOCK; q++)
        xs[q] = __ldg(x + b0 + q);

#if __CUDA_ARCH__ >= 900
    cudaGridDependencySynchronize();                 // wait for d_w
#endif

    const float4 w4 = *(const float4*)(d_w + jbase);

    #pragma unroll
    for (int q = 0; q < ROWS_PER_BLOCK; q++) {
        float xv = xs[q];
        float4 o = make_float4(xv * w4.x, xv * w4.y, xv * w4.z, xv * w4.w);
        // 134 MB output, never re-read -> streaming (evict-first) store
        __stcs((float4*)(out + (size_t)(b0 + q) * D + jbase), o);
    }
}

extern "C" void kernel_launch(void* const* d_in, const int* in_sizes, int n_in,
                              void* d_out, int out_size) {
    const float* x     = (const float*)d_in[0];  // (4096, 1)
    const float* s1    = (const float*)d_in[1];  // (8192,)
    const float* s2    = (const float*)d_in[2];  // (8192,)
    const float* g_mu  = (const float*)d_in[3];  // (8192,)
    const float* g_rho = (const float*)d_in[4];  // (8192,)
    const float* eps   = (const float*)d_in[5];  // (8192,)
    float* out = (float*)d_out;                  // (4096, 8192) f32

    cudaLaunchAttribute attr;
    attr.id = cudaLaunchAttributeProgrammaticStreamSerialization;
    attr.val.programmaticStreamSerializationAllowed = 1;

    stage1_kernel<<<16, 64>>>(s1, g_mu, g_rho, eps);

    {
        cudaLaunchConfig_t cfg = {};
        cfg.gridDim = dim3(8, 1, 1);
        cfg.blockDim = dim3(32, 1, 1);
        cfg.stream = 0;
        cfg.attrs = &attr; cfg.numAttrs = 1;
        cudaLaunchKernelEx(&cfg, stage2_kernel, s2);
    }
    {
        cudaLaunchConfig_t cfg = {};
        cfg.gridDim = dim3(D / 1024, BATCH / ROWS_PER_BLOCK, 1);  // (8, 256)
        cfg.blockDim = dim3(256, 1, 1);
        cfg.stream = 0;
        cfg.attrs = &attr; cfg.numAttrs = 1;
        cudaLaunchKernelEx(&cfg, outer_kernel, x, out);
    }
}

// round 12
// speedup vs baseline: 1.0251x; 1.0251x over previous
#include <cuda_runtime.h>
#include <cuda_bf16.h>

#define D 8192
#define BATCH 4096
#define ROWS_PER_BLOCK 16

// z: FWHT bits 7..12 applied (strides 128..4096), s1[0] folded.
__device__ float d_z[D];

// ---------------------------------------------------------------------------
// Producer: softplus + s1[0] + FWHT bits 7..12, barrier-free, register-only.
// Element e = g*128 + low (g: bits 7..12, low: bits 0..6).
// Thread = one low (lane = low % 32 -> every warp access is one 128B segment);
// all 64 g values held in registers; 6 butterfly stages fully in-register.
// 4 blocks x 32 threads. Trigger at top = R9's empirically-validated PDL
// pattern (residual 1.0us); producer runtime hides under outer's launch ramp.
// ---------------------------------------------------------------------------
__global__ __launch_bounds__(32, 1)
void producer_kernel(const float* __restrict__ s1,
                     const float* __restrict__ g_mu,
                     const float* __restrict__ g_rho,
                     const float* __restrict__ eps) {
#if __CUDA_ARCH__ >= 900
    cudaTriggerProgrammaticLaunchCompletion();   // dependent may launch now
#endif
    const int low = blockIdx.x * 32 + threadIdx.x;   // 0..127
    const float s10 = __ldg(s1);

    float r[64];
    #pragma unroll
    for (int g = 0; g < 64; g++) {               // coalesced: 128B per warp-load
        const int e = g * 128 + low;
        float v  = __ldg(g_rho + e);
        float m  = __ldg(g_mu  + e);
        float p  = __ldg(eps   + e);
        float sp = fmaxf(v, 0.0f) + __logf(1.0f + __expf(-fabsf(v)));
        r[g] = s10 * fmaf(sp, p, m);
    }

    // 64-point FWHT over g (element-index bits 7..12), all in registers
    #pragma unroll
    for (int s = 1; s < 64; s <<= 1) {
        #pragma unroll
        for (int g = 0; g < 64; g++) {
            if (!(g & s)) {
                float a = r[g], b = r[g | s];
                r[g]     = a + b;
                r[g | s] = a - b;
            }
        }
    }

    #pragma unroll
    for (int g = 0; g < 64; g++)                 // coalesced stores
        d_z[g * 128 + low] = r[g];
}

// ---------------------------------------------------------------------------
// Outer (R3's measured-best body, 21.8us): finish low-bit FWHT stages
// (strides 1..64, confined to 128-groups), apply s2, stream the rank-1
// outer product. grid (8, 256) x 256 threads, 16 rows/block, __stcs stores.
// PDL: x and s2 preloaded BEFORE the grid dependency sync.
// ---------------------------------------------------------------------------
__global__ __launch_bounds__(256)
void outer_kernel(const float* __restrict__ x,
                  const float* __restrict__ s2,
                  float* __restrict__ out) {
    __shared__ float sw[1024];
    const int tid  = threadIdx.x;
    const int lane = tid & 31;
    const int r    = tid >> 5;                    // warp = 128-group in chunk
    const int jb   = blockIdx.x * 1024;
    const int base = jb + r * 128 + lane;
    const int b0   = blockIdx.y * ROWS_PER_BLOCK;

    // ---- prologue independent of the producer ----
    float xs[ROWS_PER_BLOCK];
    #pragma unroll
    for (int q = 0; q < ROWS_PER_BLOCK; q++)
        xs[q] = __ldg(x + b0 + q);

    float s2v[4];
    #pragma unroll
    for (int k = 0; k < 4; k++)
        s2v[k] = __ldg(s2 + base + k * 32);

#if __CUDA_ARCH__ >= 900
    cudaGridDependencySynchronize();              // wait for d_z
#endif

    // ---- load z chunk (lane = bits 0..4, k = bits 5..6) ----
    float rr[4];
    #pragma unroll
    for (int k = 0; k < 4; k++)
        rr[k] = d_z[base + k * 32];

    #pragma unroll
    for (int m = 1; m <= 16; m <<= 1) {           // strides 1..16
        const float sgn = (lane & m) ? -1.0f : 1.0f;
        #pragma unroll
        for (int k = 0; k < 4; k++) {
            float o = __shfl_xor_sync(0xffffffffu, rr[k], m);
            rr[k] = fmaf(sgn, rr[k], o);
        }
    }
    { // stride 32 (k bit 0)
        float a0 = rr[0], c0 = rr[1], a1 = rr[2], c1 = rr[3];
        rr[0] = a0 + c0; rr[1] = a0 - c0;
        rr[2] = a1 + c1; rr[3] = a1 - c1;
    }
    { // stride 64 (k bit 1)
        float a0 = rr[0], c0 = rr[2], a1 = rr[1], c1 = rr[3];
        rr[0] = a0 + c0; rr[2] = a0 - c0;
        rr[1] = a1 + c1; rr[3] = a1 - c1;
    }

    // apply s2; transpose through smem so each thread owns 4 contiguous cols
    #pragma unroll
    for (int k = 0; k < 4; k++)
        sw[r * 128 + k * 32 + lane] = s2v[k] * rr[k];
    __syncthreads();

    const float4 w4 = *(const float4*)&sw[tid * 4];
    const int jbase = jb + tid * 4;

    #pragma unroll
    for (int q = 0; q < ROWS_PER_BLOCK; q++) {
        float xv = xs[q];
        float4 o = make_float4(xv * w4.x, xv * w4.y, xv * w4.z, xv * w4.w);
        // 134 MB output, never re-read -> streaming (evict-first) store
        __stcs((float4*)(out + (size_t)(b0 + q) * D + jbase), o);
    }
}

extern "C" void kernel_launch(void* const* d_in, const int* in_sizes, int n_in,
                              void* d_out, int out_size) {
    const float* x     = (const float*)d_in[0];  // (4096, 1)
    const float* s1    = (const float*)d_in[1];  // (8192,)
    const float* s2    = (const float*)d_in[2];  // (8192,)
    const float* g_mu  = (const float*)d_in[3];  // (8192,)
    const float* g_rho = (const float*)d_in[4];  // (8192,)
    const float* eps   = (const float*)d_in[5];  // (8192,)
    float* out = (float*)d_out;                  // (4096, 8192) f32

    producer_kernel<<<4, 32>>>(s1, g_mu, g_rho, eps);

    cudaLaunchConfig_t cfg = {};
    cfg.gridDim  = dim3(D / 1024, BATCH / ROWS_PER_BLOCK, 1);  // (8, 256)
    cfg.blockDim = dim3(256, 1, 1);
    cfg.stream   = 0;
    cudaLaunchAttribute attr;
    attr.id = cudaLaunchAttributeProgrammaticStreamSerialization;
    attr.val.programmaticStreamSerializationAllowed = 1;
    cfg.attrs    = &attr;
    cfg.numAttrs = 1;
    cudaLaunchKernelEx(&cfg, outer_kernel, x, s2, out);
}

// round 13
// speedup vs baseline: 1.0401x; 1.0146x over previous
#include <cuda_runtime.h>
#include <cuda_bf16.h>

#define D 8192
#define BATCH 4096
#define ROWS_PER_BLOCK 16

// z: FWHT bits 10..12 applied (strides 1024/2048/4096), s1[0] folded.
__device__ float d_z[D];

// ---------------------------------------------------------------------------
// Producer (R9's proven config, residual 1.0us): softplus + s1[0] + FWHT bits
// 10..12. Thread i owns {i + j*1024 : j=0..7}; every warp access is a perfect
// contiguous segment; 24-deep load MLP; barrier-free; 16 blocks x 64 threads.
// ---------------------------------------------------------------------------
__global__ __launch_bounds__(64, 1)
void producer_kernel(const float* __restrict__ s1,
                     const float* __restrict__ g_mu,
                     const float* __restrict__ g_rho,
                     const float* __restrict__ eps) {
#if __CUDA_ARCH__ >= 900
    cudaTriggerProgrammaticLaunchCompletion();   // dependent may launch now
#endif
    const int i = blockIdx.x * 64 + threadIdx.x;     // 0..1023
    const float s10 = __ldg(s1);

    float rh[8], mu[8], ep[8];
    #pragma unroll
    for (int j = 0; j < 8; j++) {                    // issue all loads first
        rh[j] = __ldg(g_rho + i + j * 1024);
        mu[j] = __ldg(g_mu  + i + j * 1024);
        ep[j] = __ldg(eps   + i + j * 1024);
    }
    float r[8];
    #pragma unroll
    for (int j = 0; j < 8; j++) {
        float sp = fmaxf(rh[j], 0.0f) + __logf(1.0f + __expf(-fabsf(rh[j])));
        r[j] = s10 * fmaf(sp, ep[j], mu[j]);
    }
    #pragma unroll
    for (int s = 1; s < 8; s <<= 1) {                // bits 10..12
        #pragma unroll
        for (int j = 0; j < 8; j++) {
            if (!(j & s)) {
                float a = r[j], b = r[j | s];
                r[j]     = a + b;
                r[j | s] = a - b;
            }
        }
    }
    #pragma unroll
    for (int j = 0; j < 8; j++)
        d_z[i + j * 1024] = r[j];                    // coalesced
}

// ---------------------------------------------------------------------------
// Outer: FWHT bits 0..9 + s2 + rank-1 outer product, ONE sync, NO transposes.
//   bits 0..4: shfl.xor on lane; bits 5..6: in-register over k;
//   bits 7..9: after STS, each thread combines 8 conflict-free LDS.128 reads
//     with warp-uniform signs:  w[r*128+t] = sum_c (-1)^popc(r&c) pre[c*128+t]
//   (Sylvester H_8; stages commute so bit order is free.)
// s2 applied at the end (after all stages). grid (8,256) x 256, __stcs.
// ---------------------------------------------------------------------------
__global__ __launch_bounds__(256)
void outer_kernel(const float* __restrict__ x,
                  const float* __restrict__ s2,
                  float* __restrict__ out) {
    __shared__ float sw[1024];
    const int tid  = threadIdx.x;
    const int lane = tid & 31;
    const int r    = tid >> 5;                    // warp = bits 7..9 of chunk idx
    const int jb   = blockIdx.x * 1024;
    const int base = jb + r * 128 + lane;
    const int b0   = blockIdx.y * ROWS_PER_BLOCK;

    // ---- prologue independent of the producer ----
    float xs[ROWS_PER_BLOCK];
    #pragma unroll
    for (int q = 0; q < ROWS_PER_BLOCK; q++)
        xs[q] = __ldg(x + b0 + q);
    const float4 s2q = *(const float4*)(s2 + jb + tid * 4);

#if __CUDA_ARCH__ >= 900
    cudaGridDependencySynchronize();              // wait for d_z
#endif

    // ---- load z chunk (lane = bits 0..4, k = bits 5..6) ----
    float rr[4];
    #pragma unroll
    for (int k = 0; k < 4; k++)
        rr[k] = d_z[base + k * 32];

    #pragma unroll
    for (int m = 1; m <= 16; m <<= 1) {           // bits 0..4
        const float sgn = (lane & m) ? -1.0f : 1.0f;
        #pragma unroll
        for (int k = 0; k < 4; k++) {
            float o = __shfl_xor_sync(0xffffffffu, rr[k], m);
            rr[k] = fmaf(sgn, rr[k], o);
        }
    }
    { // bit 5 (k bit 0)
        float a0 = rr[0], c0 = rr[1], a1 = rr[2], c1 = rr[3];
        rr[0] = a0 + c0; rr[1] = a0 - c0;
        rr[2] = a1 + c1; rr[3] = a1 - c1;
    }
    { // bit 6 (k bit 1)
        float a0 = rr[0], c0 = rr[2], a1 = rr[1], c1 = rr[3];
        rr[0] = a0 + c0; rr[2] = a0 - c0;
        rr[1] = a1 + c1; rr[3] = a1 - c1;
    }

    // stage partials: pre[c*128 + t], c = this warp's r, t = k*32 + lane
    #pragma unroll
    for (int k = 0; k < 4; k++)
        sw[r * 128 + k * 32 + lane] = rr[k];
    __syncthreads();

    // ---- bits 7..9: 8-way signed combine, conflict-free LDS.128 ----
    const int toff = (tid * 4) & 127;             // t for this thread's 4 cols
    float4 w4 = make_float4(0.f, 0.f, 0.f, 0.f);
    #pragma unroll
    for (int c = 0; c < 8; c++) {
        const float sgn = (__popc(r & c) & 1) ? -1.0f : 1.0f;   // warp-uniform
        const float4 p = *(const float4*)&sw[c * 128 + toff];
        w4.x = fmaf(sgn, p.x, w4.x);
        w4.y = fmaf(sgn, p.y, w4.y);
        w4.z = fmaf(sgn, p.z, w4.z);
        w4.w = fmaf(sgn, p.w, w4.w);
    }
    // s2 last (elementwise on the completed transform)
    w4.x *= s2q.x; w4.y *= s2q.y; w4.z *= s2q.z; w4.w *= s2q.w;

    const int jbase = jb + tid * 4;

    #pragma unroll
    for (int q = 0; q < ROWS_PER_BLOCK; q++) {
        float xv = xs[q];
        float4 o = make_float4(xv * w4.x, xv * w4.y, xv * w4.z, xv * w4.w);
        // 134 MB output, never re-read -> streaming (evict-first) store
        __stcs((float4*)(out + (size_t)(b0 + q) * D + jbase), o);
    }
}

extern "C" void kernel_launch(void* const* d_in, const int* in_sizes, int n_in,
                              void* d_out, int out_size) {
    const float* x     = (const float*)d_in[0];  // (4096, 1)
    const float* s1    = (const float*)d_in[1];  // (8192,)
    const float* s2    = (const float*)d_in[2];  // (8192,)
    const float* g_mu  = (const float*)d_in[3];  // (8192,)
    const float* g_rho = (const float*)d_in[4];  // (8192,)
    const float* eps   = (const float*)d_in[5];  // (8192,)
    float* out = (float*)d_out;                  // (4096, 8192) f32

    producer_kernel<<<16, 64>>>(s1, g_mu, g_rho, eps);

    cudaLaunchConfig_t cfg = {};
    cfg.gridDim  = dim3(D / 1024, BATCH / ROWS_PER_BLOCK, 1);  // (8, 256)
    cfg.blockDim = dim3(256, 1, 1);
    cfg.stream   = 0;
    cudaLaunchAttribute attr;
    attr.id = cudaLaunchAttributeProgrammaticStreamSerialization;
    attr.val.programmaticStreamSerializationAllowed = 1;
    cfg.attrs    = &attr;
    cfg.numAttrs = 1;
    cudaLaunchKernelEx(&cfg, outer_kernel, x, s2, out);
}